// round 12
// baseline (speedup 1.0000x reference)
#include <cuda_runtime.h>
#include <cuda_fp16.h>
#include <math.h>

#define NPATHS 15
#define CG_TOTAL 615
#define MAXE 1000000
#define EPAD 1425984          // MAXE + 8*NPAD, multiple of 8 (row pitch)
#define NPAD 53248            // 13 * 4096, >= N
#define TABN 16384            // gate table intervals over [0, 2]
#define NB_CG 15
#define NB_TAB 65             // covers TABN+1 = 16385 at 256/block

// path tables: (l1,l2,l3) enumerated as in the reference (l1 outer, l2 mid, l3 inner)
__device__ constexpr int PL1[NPATHS]  = {0,0,0,1,1,1,1,1,1,2,2,2,2,2,2};
__device__ constexpr int PL2[NPATHS]  = {0,1,2,0,1,1,1,2,2,0,1,1,2,2,2};
__device__ constexpr int PL3[NPATHS]  = {0,1,2,1,0,1,2,1,2,2,1,2,0,1,2};
__device__ constexpr int CGO[NPATHS]  = {0,1,10,35,44,53,80,125,170,245,270,315,390,415,490};
__device__ constexpr int GEOO[NPATHS] = {0,1,4,9,12,13,16,21,24,29,34,37,42,43,46};
__device__ constexpr int LOFF[3] = {0,1,4};

__device__ float g_cg[CG_TOTAL];
__device__ __align__(16) float g_Ai[NPAD * 8];
__device__ __align__(16) __half g_AiH[(size_t)8 * EPAD];   // [m][slot], fp16; pads zeroed
__device__ __align__(16) __half g_geoH[(size_t)52 * EPAD]; // [pj][slot], fp16; pads stay 0
__device__ __align__(16) float g_tab[(TABN + 1) * 16];     // gate table (alpha*inv_avg baked)
__device__ __align__(16) float4 g_edata[MAXE];             // {sx,sy,sz, bitcast(src)} per slot
__device__ int   g_dstS[MAXE];                             // dst per slot (sorted)
__device__ __align__(16) int g_count[NPAD];                // zero at entry; re-zeroed by scan
__device__ __align__(16) int g_off[NPAD + 4];              // 8-aligned starts
__device__ __align__(16) int g_end[NPAD + 4];              // off + count
__device__ __align__(16) int g_cursor[NPAD];

// ---------------------------------------------------------------------------
// CG math helpers (double precision, replicates the reference)
// ---------------------------------------------------------------------------
__device__ double dfact(int n) {
    double r = 1.0;
    for (int i = 2; i <= n; ++i) r *= (double)i;
    return r;
}

__device__ double cgc(int j1, int j2, int j3, int m1, int m2, int m3) {
    if (m1 + m2 != m3) return 0.0;
    double pre = sqrt((double)(2 * j3 + 1) * dfact(j3 + j1 - j2) * dfact(j3 - j1 + j2) *
                      dfact(j1 + j2 - j3) / dfact(j1 + j2 + j3 + 1));
    pre *= sqrt(dfact(j3 + m3) * dfact(j3 - m3) * dfact(j1 - m1) * dfact(j1 + m1) *
                dfact(j2 - m2) * dfact(j2 + m2));
    double s = 0.0;
    for (int k = 0; k <= j1 + j2 - j3; ++k) {
        int d1 = j1 + j2 - j3 - k, d2 = j1 - m1 - k, d3 = j2 + m2 - k;
        int d4 = j3 - j2 + m1 + k, d5 = j3 - j1 - m2 + k;
        if (d1 < 0 || d2 < 0 || d3 < 0 || d4 < 0 || d5 < 0) continue;
        double t = 1.0 / (dfact(k) * dfact(d1) * dfact(d2) * dfact(d3) * dfact(d4) * dfact(d5));
        s += (k & 1) ? -t : t;
    }
    return pre * s;
}

__device__ void buildq(int l, double qr[5][5], double qi[5][5]) {
    for (int a = 0; a < 5; a++)
        for (int b = 0; b < 5; b++) { qr[a][b] = 0.0; qi[a][b] = 0.0; }
    const double isq = sqrt(0.5);
    for (int m = -l; m < 0; m++) {
        qr[l + m][l - m] = isq;
        qi[l + m][l + m] = -isq;
    }
    qr[l][l] = 1.0;
    for (int m = 1; m <= l; m++) {
        double sg = (m & 1) ? -1.0 : 1.0;
        qr[l + m][l + m] = sg * isq;
        qi[l + m][l - m] = sg * isq;
    }
    if (l == 1) {
        for (int a = 0; a < 5; a++)
            for (int b = 0; b < 5; b++) {
                double r = qr[a][b], i0 = qi[a][b];
                qr[a][b] = i0;
                qi[a][b] = -r;
            }
    } else if (l == 2) {
        for (int a = 0; a < 5; a++)
            for (int b = 0; b < 5; b++) { qr[a][b] = -qr[a][b]; qi[a][b] = -qi[a][b]; }
    }
}

// ---------------------------------------------------------------------------
// Mega init kernel: CG init / gate table / node MLP / edge histogram / AiH zero.
// ---------------------------------------------------------------------------
__global__ void __launch_bounds__(256) mega_init_kernel(
    const float* __restrict__ fw1, const float* __restrict__ fb1,
    const float* __restrict__ fw2, const float* __restrict__ fb2,
    const float* __restrict__ fw3, const float* __restrict__ fb3,
    float inv_avg,
    const float* __restrict__ emb_table, const int* __restrict__ A,
    const float* __restrict__ mw1, const float* __restrict__ mb1,
    const float* __restrict__ mw2, const float* __restrict__ mb2,
    const int* __restrict__ edst,
    int N, int E, int nbNode, int nbHist)
{
    __shared__ __align__(16) unsigned char sbuf[23040];
    int b = blockIdx.x;
    int tid = threadIdx.x;

    if (b < NB_CG) {
        double* q1r = (double*)(sbuf);
        double* q1i = q1r + 25;
        double* q2r = q1i + 25;
        double* q2i = q2r + 25;
        double* q3r = q2i + 25;
        double* q3i = q3r + 25;
        float* sAr = (float*)(q3i + 25);
        float* sAi = sAr + 128;
        int* sUseRe = (int*)(sAi + 128);

        int p = b;
        int l1 = PL1[p], l2 = PL2[p], l3 = PL3[p];
        int n1 = 2 * l1 + 1, n2 = 2 * l2 + 1, n3 = 2 * l3 + 1;
        int tot = n1 * n2 * n3;

        if (tid < 3) {
            double qr[5][5], qi[5][5];
            int l = (tid == 0) ? l1 : (tid == 1) ? l2 : l3;
            buildq(l, qr, qi);
            double* dr = (tid == 0) ? q1r : (tid == 1) ? q2r : q3r;
            double* di = (tid == 0) ? q1i : (tid == 1) ? q2i : q3i;
            for (int a = 0; a < 5; a++)
                for (int c = 0; c < 5; c++) { dr[a * 5 + c] = qr[a][c]; di[a * 5 + c] = qi[a][c]; }
        }
        __syncthreads();

        double ar = 0.0, ai = 0.0;
        if (tid < tot) {
            int i = tid / (n2 * n3);
            int rem = tid - i * (n2 * n3);
            int j = rem / n3;
            int k = rem - j * n3;
            for (int a = 0; a < n1; a++)
                for (int c = 0; c < n2; c++) {
                    double t12r = q1r[a * 5 + i] * q2r[c * 5 + j] - q1i[a * 5 + i] * q2i[c * 5 + j];
                    double t12i = q1r[a * 5 + i] * q2i[c * 5 + j] + q1i[a * 5 + i] * q2r[c * 5 + j];
                    if (t12r == 0.0 && t12i == 0.0) continue;
                    for (int cc = 0; cc < n3; cc++) {
                        double C = cgc(l1, l2, l3, a - l1, c - l2, cc - l3);
                        if (C == 0.0) continue;
                        double t3r = q3r[cc * 5 + k], t3i = -q3i[cc * 5 + k];
                        ar += (t12r * t3r - t12i * t3i) * C;
                        ai += (t12r * t3i + t12i * t3r) * C;
                    }
                }
        }
        if (tid < 128) {
            sAr[tid] = (tid < tot) ? (float)fabs(ar) : 0.0f;
            sAi[tid] = (tid < tot) ? (float)fabs(ai) : 0.0f;
        }
        __syncthreads();
        if (tid == 0) {
            float sr = 0.0f, si = 0.0f;
            for (int q = 0; q < tot; q++) { sr += sAr[q]; si += sAi[q]; }
            *sUseRe = (sr >= si) ? 1 : 0;
        }
        __syncthreads();
        if (tid < tot)
            g_cg[CGO[p] + tid] = (float)(*sUseRe ? ar : ai);
        return;
    }
    b -= NB_CG;

    if (b < NB_TAB) {
        float* F = (float*)sbuf;
        float* sW1 = F;
        float* sB1 = F + 512;
        float* sB2 = F + 576;
        float* sW2 = F + 640;
        float* sW3 = F + 4736;
        float* sB3 = F + 5696;

        for (int i = tid; i < 8 * 64; i += 256) sW1[i] = fw1[i];
        for (int i = tid; i < 64; i += 256) { sB1[i] = fb1[i]; sB2[i] = fb2[i]; }
        for (int i = tid; i < 64 * 64; i += 256) sW2[i] = fw2[i];
        for (int i = tid; i < 64 * NPATHS; i += 256) sW3[i] = fw3[i];
        for (int i = tid; i < NPATHS; i += 256) sB3[i] = fb3[i];
        __syncthreads();

        int idx = b * 256 + tid;
        if (idx > TABN) return;
        float len = (float)idx * (2.0f / (float)TABN);

        float emb[8];
        const float step = 2.0f / 9.0f;
        const float istep = 4.5f;
        const float cemb = 2.8284271247461903f / 1.12f;
#pragma unroll
        for (int i = 0; i < 8; i++) {
            float t = (len - (float)(i + 1) * step) * istep;
            emb[i] = __expf(-t * t) * cemb;
        }

        float h1[64];
#pragma unroll
        for (int j = 0; j < 64; j++) {
            float t = sB1[j];
#pragma unroll
            for (int i = 0; i < 8; i++) t += emb[i] * sW1[i * 64 + j];
            h1[j] = t / (1.0f + __expf(-t));
        }

        float gp[NPATHS];
#pragma unroll
        for (int p = 0; p < NPATHS; p++) gp[p] = sB3[p];
#pragma unroll 4
        for (int j = 0; j < 64; j++) {
            float t = sB2[j];
#pragma unroll
            for (int i = 0; i < 64; i++) t += h1[i] * sW2[i * 64 + j];
            float s = t / (1.0f + __expf(-t));
#pragma unroll
            for (int p = 0; p < NPATHS; p++) gp[p] += s * sW3[j * NPATHS + p];
        }

        const float ALP0 = 0.20412414523193154f;
        const float ALP1 = 0.14433756729740643f;
        float* row = g_tab + (size_t)idx * 16;
#pragma unroll
        for (int p = 0; p < NPATHS; p++) {
            float alpha = (PL3[p] == 0) ? ALP0 : ALP1;
            row[p] = gp[p] * alpha * inv_avg;
        }
        row[15] = 0.0f;
        return;
    }
    b -= NB_TAB;

    if (b < nbNode) {
        float* F = (float*)sbuf;
        float* sW1 = F;
        float* sB1 = F + 1024;
        float* sW2 = F + 1088;
        float* sB2 = F + 1600;
        float* sEmb = F + 1608;

        for (int i = tid; i < 16 * 64; i += 256) sW1[i] = mw1[i];
        for (int i = tid; i < 64; i += 256) sB1[i] = mb1[i];
        for (int i = tid; i < 64 * 8; i += 256) sW2[i] = mw2[i];
        for (int i = tid; i < 8; i += 256) sB2[i] = mb2[i];
        for (int i = tid; i < 10 * 16; i += 256) sEmb[i] = emb_table[i];
        __syncthreads();

        int n = b * 256 + tid;
        if (n >= N) return;
        int a = A[n];
        float x[16];
#pragma unroll
        for (int i = 0; i < 16; i++) x[i] = sEmb[a * 16 + i];
        float h[64];
#pragma unroll
        for (int j = 0; j < 64; j++) {
            float t = sB1[j];
#pragma unroll
            for (int i = 0; i < 16; i++) t += x[i] * sW1[i * 64 + j];
            h[j] = t / (1.0f + __expf(-t));
        }
#pragma unroll
        for (int o = 0; o < 8; o++) {
            float t = sB2[o];
#pragma unroll
            for (int j = 0; j < 64; j++) t += h[j] * sW2[j * 8 + o];
            g_Ai[n * 8 + o] = t;
        }
        return;
    }
    b -= nbNode;

    if (b < nbHist) {
        // ----- edge histogram (counts pre-zeroed) -----
        int e = b * 256 + tid;
        if (e < E) atomicAdd(&g_count[edst[e]], 1);
        return;
    }
    b -= nbHist;

    // ----- zero AiH (pads must be 0; real slots rewritten by geo) -----
    size_t i = (size_t)b * 256 + tid;   // one int4 = 8 halves per thread
    if (i < EPAD) ((int4*)g_AiH)[i] = make_int4(0, 0, 0, 0);
}

// ---------------------------------------------------------------------------
// Coalesced exclusive scan over ALIGNED counts ((c+7)&~7). Writes 8-aligned
// starts to g_off/g_cursor, real ends to g_end, re-zeros g_count.
// ---------------------------------------------------------------------------
__global__ void __launch_bounds__(1024) scan_kernel() {
    __shared__ int warpsums[32];
    __shared__ int sCarry;
    int t = threadIdx.x;
    int lane = t & 31, wid = t >> 5;
    if (t == 0) sCarry = 0;
    __syncthreads();

#pragma unroll 1
    for (int base = 0; base < NPAD; base += 4096) {
        int4 v = *(const int4*)(g_count + base + t * 4);
        *(int4*)(g_count + base + t * 4) = make_int4(0, 0, 0, 0);  // re-zero for next replay
        int4 pv;
        pv.x = (v.x + 7) & ~7;
        pv.y = (v.y + 7) & ~7;
        pv.z = (v.z + 7) & ~7;
        pv.w = (v.w + 7) & ~7;
        int s = pv.x + pv.y + pv.z + pv.w;
        int ss = s;
#pragma unroll
        for (int d = 1; d < 32; d <<= 1) {
            int o = __shfl_up_sync(0xffffffffu, ss, d);
            if (lane >= d) ss += o;
        }
        if (lane == 31) warpsums[wid] = ss;
        __syncthreads();
        if (wid == 0) {
            int w = warpsums[lane];
#pragma unroll
            for (int d = 1; d < 32; d <<= 1) {
                int o = __shfl_up_sync(0xffffffffu, w, d);
                if (lane >= d) w += o;
            }
            warpsums[lane] = w;
        }
        __syncthreads();
        int carry = sCarry;
        int excl = carry + (wid ? warpsums[wid - 1] : 0) + (ss - s);
        int4 o;
        o.x = excl;
        o.y = excl + pv.x;
        o.z = o.y + pv.y;
        o.w = o.z + pv.z;
        *(int4*)(g_off + base + t * 4) = o;
        *(int4*)(g_cursor + base + t * 4) = o;
        int4 en;
        en.x = o.x + v.x;
        en.y = o.y + v.y;
        en.z = o.z + v.z;
        en.w = o.w + v.w;
        *(int4*)(g_end + base + t * 4) = en;
        int total = warpsums[31];
        __syncthreads();
        if (t == 0) sCarry = carry + total;
        __syncthreads();
    }
}

__global__ void scatter_kernel(const int* __restrict__ esrc,
                               const int* __restrict__ edst,
                               const float* __restrict__ eshift, int E) {
    int e = blockIdx.x * blockDim.x + threadIdx.x;
    if (e >= E) return;
    int d = edst[e];
    int s = esrc[e];
    float sx = eshift[e * 3 + 0], sy = eshift[e * 3 + 1], sz = eshift[e * 3 + 2];
    int p = atomicAdd(&g_cursor[d], 1);
    g_edata[p - (p / EPAD) * 0] = make_float4(sx, sy, sz, __int_as_float(s)); // p < 1.38M but edata sized MAXE... see note
    g_dstS[p] = d;
}

// NOTE: g_edata/g_dstS are indexed by padded slot p which can reach ~1.38M.
// They are sized EPAD below via a second declaration-free trick is impossible;
// instead we size them EPAD directly (see definitions above being MAXE —
// corrected here by using EPAD for both).

// ---------------------------------------------------------------------------
// Geo kernel: grid covers padded slot space; slots with no record (pads) are
// detected via slot >= end of owning node — instead we simply only process
// slots < E_padded that scatter wrote. We track written slots via g_dstS
// initialized to -1? Simpler: geo iterates over ORIGINAL edges' padded slots
// stored compactly: scatter wrote records at padded positions; pads hold
// stale/unwritten records. To keep geo at exactly E threads, scatter also
// appends the padded position into a dense list g_slotOf[e]. geo thread e
// reads g_slotOf[e] and writes its outputs at that padded slot.
// ---------------------------------------------------------------------------
__device__ int g_slotOf[MAXE];

__global__ void __launch_bounds__(256) geo_kernel(
    const float* __restrict__ pos, const int* __restrict__ batch,
    const float* __restrict__ cell, int E)
{
    __shared__ float sCG[CG_TOTAL];
    int tid = threadIdx.x;
    for (int i = tid; i < CG_TOTAL; i += 256) sCG[i] = g_cg[i];
    __syncthreads();

    int e = blockIdx.x * 256 + tid;
    if (e >= E) return;
    int slot = g_slotOf[e];
    float4 rec = g_edata[e];
    int s = __float_as_int(rec.w);
    int d = g_dstS[e];

    {
        const float4* ap = (const float4*)(g_Ai + (size_t)s * 8);
        float4 a0 = ap[0], a1 = ap[1];
        g_AiH[(size_t)0 * EPAD + slot] = __float2half_rn(a0.x);
        g_AiH[(size_t)1 * EPAD + slot] = __float2half_rn(a0.y);
        g_AiH[(size_t)2 * EPAD + slot] = __float2half_rn(a0.z);
        g_AiH[(size_t)3 * EPAD + slot] = __float2half_rn(a0.w);
        g_AiH[(size_t)4 * EPAD + slot] = __float2half_rn(a1.x);
        g_AiH[(size_t)5 * EPAD + slot] = __float2half_rn(a1.y);
        g_AiH[(size_t)6 * EPAD + slot] = __float2half_rn(a1.z);
        g_AiH[(size_t)7 * EPAD + slot] = __float2half_rn(a1.w);
    }

    int b = batch[s];
    const float* cl = cell + b * 9;
    float shx = rec.x * cl[0] + rec.y * cl[3] + rec.z * cl[6];
    float shy = rec.x * cl[1] + rec.y * cl[4] + rec.z * cl[7];
    float shz = rec.x * cl[2] + rec.y * cl[5] + rec.z * cl[8];
    float vx = pos[d * 3 + 0] - pos[s * 3 + 0] + shx;
    float vy = pos[d * 3 + 1] - pos[s * 3 + 1] + shy;
    float vz = pos[d * 3 + 2] - pos[s * 3 + 2] + shz;
    float L = sqrtf(vx * vx + vy * vy + vz * vz);
    float il = 1.0f / fmaxf(L, 1e-8f);
    float nx = vx * il, ny = vy * il, nz = vz * il;

    float Yv[9];
    const float s3 = 1.7320508075688772f;
    const float s15 = 3.872983346207417f;
    const float s5 = 2.23606797749979f;
    Yv[0] = 1.0f;
    Yv[1] = s3 * ny; Yv[2] = s3 * nz; Yv[3] = s3 * nx;
    Yv[4] = s15 * nx * ny;
    Yv[5] = s15 * ny * nz;
    Yv[6] = 0.5f * s5 * (3.0f * nz * nz - 1.0f);
    Yv[7] = s15 * nx * nz;
    Yv[8] = 0.5f * s15 * (nx * nx - ny * ny);

    float gp[16];
    {
        float t = L * ((float)TABN / 2.0f);
        int i0 = (int)t;
        i0 = min(i0, TABN - 1);
        float f = t - (float)i0;
        const float4* t0 = (const float4*)(g_tab + (size_t)i0 * 16);
        const float4* t1 = (const float4*)(g_tab + (size_t)(i0 + 1) * 16);
#pragma unroll
        for (int q = 0; q < 4; q++) {
            float4 a = t0[q], c = t1[q];
            gp[q * 4 + 0] = a.x + f * (c.x - a.x);
            gp[q * 4 + 1] = a.y + f * (c.y - a.y);
            gp[q * 4 + 2] = a.z + f * (c.z - a.z);
            gp[q * 4 + 3] = a.w + f * (c.w - a.w);
        }
    }

#pragma unroll
    for (int p = 0; p < NPATHS; p++) {
        const int l1 = PL1[p], l2 = PL2[p], l3 = PL3[p];
        const int o1 = LOFF[l1], o2 = LOFF[l2];
        const int n2d = 2 * l2 + 1, n3d = 2 * l3 + 1;
        float acc[5];
#pragma unroll
        for (int k = 0; k < 5; k++) acc[k] = 0.0f;
#pragma unroll
        for (int m = 0; m < 2 * l1 + 1; m++) {
#pragma unroll
            for (int n = 0; n < 2 * l2 + 1; n++) {
                float t = Yv[o1 + m] * Yv[o2 + n];
#pragma unroll
                for (int k = 0; k < 2 * l3 + 1; k++)
                    acc[k] += t * sCG[CGO[p] + (m * n2d + n) * n3d + k];
            }
        }
#pragma unroll
        for (int k = 0; k < 2 * l3 + 1; k++)
            g_geoH[(size_t)(GEOO[p] + k) * EPAD + slot] = __float2half_rn(acc[k] * gp[p]);
    }
}

// scatter writes dense records at index e and padded slot into g_slotOf.
__global__ void scatter_kernel2(const int* __restrict__ esrc,
                                const int* __restrict__ edst,
                                const float* __restrict__ eshift, int E) {
    int e = blockIdx.x * blockDim.x + threadIdx.x;
    if (e >= E) return;
    int d = edst[e];
    int s = esrc[e];
    float sx = eshift[e * 3 + 0], sy = eshift[e * 3 + 1], sz = eshift[e * 3 + 2];
    int p = atomicAdd(&g_cursor[d], 1);
    g_edata[e] = make_float4(sx, sy, sz, __int_as_float(s));
    g_dstS[e] = d;
    g_slotOf[e] = p;
}

// ---------------------------------------------------------------------------
// Accum+finalize fused: warp per node, ALL-VECTOR loop (8-aligned, zero pads).
// ---------------------------------------------------------------------------
__global__ void __launch_bounds__(256) accum_finalize_kernel(
    const float* __restrict__ tpw, float* __restrict__ out, int N)
{
    __shared__ float sS[8][416];
    __shared__ float sTP[NPATHS * 8 * 16];
    int tid = threadIdx.x;
    for (int i = tid; i < NPATHS * 8 * 16; i += 256) sTP[i] = tpw[i];
    __syncthreads();

    int warp = tid >> 5;
    int lane = tid & 31;
    int n = blockIdx.x * 8 + warp;
    int m = lane & 7;
    int q = lane >> 3;           // 0..3
    int base_pj = q * 13;        // pj 51 is a zero row (padding)
    if (n >= N) return;

    {
        int lo = g_off[n], end = g_end[n];
        const __half* aim = g_AiH + (size_t)m * EPAD;

        float acc[13];
#pragma unroll
        for (int r = 0; r < 13; r++) acc[r] = 0.0f;

        for (int i = lo; i < end; i += 8) {
            float4 av = *(const float4*)(aim + i);
            const __half2* ah = (const __half2*)&av;
            float af[8];
#pragma unroll
            for (int k = 0; k < 4; k++) {
                float2 f = __half22float2(ah[k]);
                af[2 * k] = f.x;
                af[2 * k + 1] = f.y;
            }
#pragma unroll
            for (int r = 0; r < 13; r++) {
                float4 gv = *(const float4*)(g_geoH + (size_t)(base_pj + r) * EPAD + i);
                const __half2* gh = (const __half2*)&gv;
#pragma unroll
                for (int k = 0; k < 4; k++) {
                    float2 gf = __half22float2(gh[k]);
                    acc[r] += af[2 * k] * gf.x + af[2 * k + 1] * gf.y;
                }
            }
        }

        float* srow = &sS[warp][m * 52 + base_pj];
#pragma unroll
        for (int r = 0; r < 13; r++) srow[r] = acc[r];
    }
    __syncwarp();

    if (lane >= 16) return;
    int c = lane;
    const float* S = sS[warp];
    float* orow = out + (size_t)n * 144;

    const int P0[3] = {0, 4, 12};
    const int G0[3] = {0, 12, 42};
    const int P1[6] = {1, 3, 5, 7, 10, 13};
    const int G1[6] = {1, 9, 13, 21, 34, 43};
    const int P2[6] = {2, 6, 8, 9, 11, 14};
    const int G2[6] = {4, 16, 24, 29, 37, 46};

    {
        float a = 0.0f;
#pragma unroll
        for (int i = 0; i < 3; i++) {
            int p = P0[i], g = G0[i];
#pragma unroll
            for (int m2 = 0; m2 < 8; m2++)
                a += sTP[(p * 8 + m2) * 16 + c] * S[m2 * 52 + g];
        }
        orow[c] = a;
    }
#pragma unroll
    for (int k = 0; k < 3; k++) {
        float a = 0.0f;
#pragma unroll
        for (int i = 0; i < 6; i++) {
            int p = P1[i], g = G1[i] + k;
#pragma unroll
            for (int m2 = 0; m2 < 8; m2++)
                a += sTP[(p * 8 + m2) * 16 + c] * S[m2 * 52 + g];
        }
        orow[16 + 3 * c + k] = a;
    }
#pragma unroll
    for (int k = 0; k < 5; k++) {
        float a = 0.0f;
#pragma unroll
        for (int i = 0; i < 6; i++) {
            int p = P2[i], g = G2[i] + k;
#pragma unroll
            for (int m2 = 0; m2 < 8; m2++)
                a += sTP[(p * 8 + m2) * 16 + c] * S[m2 * 52 + g];
        }
        orow[64 + 5 * c + k] = a;
    }
}

// ---------------------------------------------------------------------------
extern "C" void kernel_launch(void* const* d_in, const int* in_sizes, int n_in,
                              void* d_out, int out_size)
{
    const float* pos    = (const float*)d_in[0];
    const int*   A      = (const int*)d_in[1];
    const int*   batch  = (const int*)d_in[2];
    const int*   esrc   = (const int*)d_in[3];
    const int*   edst   = (const int*)d_in[4];
    const float* eshift = (const float*)d_in[5];
    const float* cell   = (const float*)d_in[6];
    const float* embt   = (const float*)d_in[7];
    const float* mw1    = (const float*)d_in[8];
    const float* mb1    = (const float*)d_in[9];
    const float* mw2    = (const float*)d_in[10];
    const float* mb2    = (const float*)d_in[11];
    const float* fw1    = (const float*)d_in[12];
    const float* fb1    = (const float*)d_in[13];
    const float* fw2    = (const float*)d_in[14];
    const float* fb2    = (const float*)d_in[15];
    const float* fw3    = (const float*)d_in[16];
    const float* fb3    = (const float*)d_in[17];
    const float* tpw    = (const float*)d_in[18];
    float* out = (float*)d_out;

    int N = in_sizes[1];
    int E = in_sizes[3];
    float avg = (float)E / (float)N;
    float inv_avg = 1.0f / fmaxf(avg, 1e-8f);

    int nbNode = (N + 255) / 256;
    int nbHist = (E + 255) / 256;
    int nbZeroA = (EPAD + 255) / 256;
    int megaBlocks = NB_CG + NB_TAB + nbNode + nbHist + nbZeroA;

    mega_init_kernel<<<megaBlocks, 256>>>(fw1, fb1, fw2, fb2, fw3, fb3, inv_avg,
                                          embt, A, mw1, mb1, mw2, mb2, edst,
                                          N, E, nbNode, nbHist);
    scan_kernel<<<1, 1024>>>();
    scatter_kernel2<<<(E + 255) / 256, 256>>>(esrc, edst, eshift, E);
    geo_kernel<<<(E + 255) / 256, 256>>>(pos, batch, cell, E);
    accum_finalize_kernel<<<(N + 7) / 8, 256>>>(tpw, out, N);
}

// round 13
// speedup vs baseline: 3.0600x; 3.0600x over previous
#include <cuda_runtime.h>
#include <cuda_fp16.h>
#include <math.h>

#define NPATHS 15
#define CG_TOTAL 615
#define MAXE 1000000
#define EPAD 1425984          // >= MAXE + 8*NPAD-ish bound, multiple of 8 (row pitch)
#define NPAD 53248            // 13 * 4096, >= N
#define TABN 16384            // gate table intervals over [0, 2]
#define NB_CG 15
#define NB_TAB 65             // covers TABN+1 = 16385 at 256/block

// path tables: (l1,l2,l3) enumerated as in the reference (l1 outer, l2 mid, l3 inner)
__device__ constexpr int PL1[NPATHS]  = {0,0,0,1,1,1,1,1,1,2,2,2,2,2,2};
__device__ constexpr int PL2[NPATHS]  = {0,1,2,0,1,1,1,2,2,0,1,1,2,2,2};
__device__ constexpr int PL3[NPATHS]  = {0,1,2,1,0,1,2,1,2,2,1,2,0,1,2};
__device__ constexpr int CGO[NPATHS]  = {0,1,10,35,44,53,80,125,170,245,270,315,390,415,490};
__device__ constexpr int GEOO[NPATHS] = {0,1,4,9,12,13,16,21,24,29,34,37,42,43,46};
__device__ constexpr int LOFF[3] = {0,1,4};

__device__ float g_cg[CG_TOTAL];
__device__ __align__(16) float g_Ai[NPAD * 8];
__device__ __align__(16) __half g_AiH[(size_t)8 * EPAD];   // [m][slot]; pad slots zeroed by geo
__device__ __align__(16) __half g_geoH[(size_t)52 * EPAD]; // [pj][slot]; pads stale-but-finite
__device__ __align__(16) float g_tab[(TABN + 1) * 16];     // gate table (alpha*inv_avg baked)
__device__ __align__(16) float4 g_edata[EPAD];             // {sx,sy,sz, bitcast(src)} per slot
__device__ __align__(16) int g_dstS[EPAD];                 // dst per slot; -1 for pad slots
__device__ __align__(16) int g_count[NPAD];                // zero at entry; re-zeroed by scan
__device__ __align__(16) int g_off[NPAD + 4];              // 8-aligned starts
__device__ __align__(16) int g_cursor[NPAD];

// ---------------------------------------------------------------------------
// CG math helpers (double precision, replicates the reference)
// ---------------------------------------------------------------------------
__device__ double dfact(int n) {
    double r = 1.0;
    for (int i = 2; i <= n; ++i) r *= (double)i;
    return r;
}

__device__ double cgc(int j1, int j2, int j3, int m1, int m2, int m3) {
    if (m1 + m2 != m3) return 0.0;
    double pre = sqrt((double)(2 * j3 + 1) * dfact(j3 + j1 - j2) * dfact(j3 - j1 + j2) *
                      dfact(j1 + j2 - j3) / dfact(j1 + j2 + j3 + 1));
    pre *= sqrt(dfact(j3 + m3) * dfact(j3 - m3) * dfact(j1 - m1) * dfact(j1 + m1) *
                dfact(j2 - m2) * dfact(j2 + m2));
    double s = 0.0;
    for (int k = 0; k <= j1 + j2 - j3; ++k) {
        int d1 = j1 + j2 - j3 - k, d2 = j1 - m1 - k, d3 = j2 + m2 - k;
        int d4 = j3 - j2 + m1 + k, d5 = j3 - j1 - m2 + k;
        if (d1 < 0 || d2 < 0 || d3 < 0 || d4 < 0 || d5 < 0) continue;
        double t = 1.0 / (dfact(k) * dfact(d1) * dfact(d2) * dfact(d3) * dfact(d4) * dfact(d5));
        s += (k & 1) ? -t : t;
    }
    return pre * s;
}

__device__ void buildq(int l, double qr[5][5], double qi[5][5]) {
    for (int a = 0; a < 5; a++)
        for (int b = 0; b < 5; b++) { qr[a][b] = 0.0; qi[a][b] = 0.0; }
    const double isq = sqrt(0.5);
    for (int m = -l; m < 0; m++) {
        qr[l + m][l - m] = isq;
        qi[l + m][l + m] = -isq;
    }
    qr[l][l] = 1.0;
    for (int m = 1; m <= l; m++) {
        double sg = (m & 1) ? -1.0 : 1.0;
        qr[l + m][l + m] = sg * isq;
        qi[l + m][l - m] = sg * isq;
    }
    if (l == 1) {
        for (int a = 0; a < 5; a++)
            for (int b = 0; b < 5; b++) {
                double r = qr[a][b], i0 = qi[a][b];
                qr[a][b] = i0;
                qi[a][b] = -r;
            }
    } else if (l == 2) {
        for (int a = 0; a < 5; a++)
            for (int b = 0; b < 5; b++) { qr[a][b] = -qr[a][b]; qi[a][b] = -qi[a][b]; }
    }
}

// ---------------------------------------------------------------------------
// Mega init: CG init / gate table / node MLP / edge histogram / dstS = -1.
// ---------------------------------------------------------------------------
__global__ void __launch_bounds__(256) mega_init_kernel(
    const float* __restrict__ fw1, const float* __restrict__ fb1,
    const float* __restrict__ fw2, const float* __restrict__ fb2,
    const float* __restrict__ fw3, const float* __restrict__ fb3,
    float inv_avg,
    const float* __restrict__ emb_table, const int* __restrict__ A,
    const float* __restrict__ mw1, const float* __restrict__ mb1,
    const float* __restrict__ mw2, const float* __restrict__ mb2,
    const int* __restrict__ edst,
    int N, int E, int nbNode, int nbHist)
{
    __shared__ __align__(16) unsigned char sbuf[23040];
    int b = blockIdx.x;
    int tid = threadIdx.x;

    if (b < NB_CG) {
        double* q1r = (double*)(sbuf);
        double* q1i = q1r + 25;
        double* q2r = q1i + 25;
        double* q2i = q2r + 25;
        double* q3r = q2i + 25;
        double* q3i = q3r + 25;
        float* sAr = (float*)(q3i + 25);
        float* sAi = sAr + 128;
        int* sUseRe = (int*)(sAi + 128);

        int p = b;
        int l1 = PL1[p], l2 = PL2[p], l3 = PL3[p];
        int n1 = 2 * l1 + 1, n2 = 2 * l2 + 1, n3 = 2 * l3 + 1;
        int tot = n1 * n2 * n3;

        if (tid < 3) {
            double qr[5][5], qi[5][5];
            int l = (tid == 0) ? l1 : (tid == 1) ? l2 : l3;
            buildq(l, qr, qi);
            double* dr = (tid == 0) ? q1r : (tid == 1) ? q2r : q3r;
            double* di = (tid == 0) ? q1i : (tid == 1) ? q2i : q3i;
            for (int a = 0; a < 5; a++)
                for (int c = 0; c < 5; c++) { dr[a * 5 + c] = qr[a][c]; di[a * 5 + c] = qi[a][c]; }
        }
        __syncthreads();

        double ar = 0.0, ai = 0.0;
        if (tid < tot) {
            int i = tid / (n2 * n3);
            int rem = tid - i * (n2 * n3);
            int j = rem / n3;
            int k = rem - j * n3;
            for (int a = 0; a < n1; a++)
                for (int c = 0; c < n2; c++) {
                    double t12r = q1r[a * 5 + i] * q2r[c * 5 + j] - q1i[a * 5 + i] * q2i[c * 5 + j];
                    double t12i = q1r[a * 5 + i] * q2i[c * 5 + j] + q1i[a * 5 + i] * q2r[c * 5 + j];
                    if (t12r == 0.0 && t12i == 0.0) continue;
                    for (int cc = 0; cc < n3; cc++) {
                        double C = cgc(l1, l2, l3, a - l1, c - l2, cc - l3);
                        if (C == 0.0) continue;
                        double t3r = q3r[cc * 5 + k], t3i = -q3i[cc * 5 + k];
                        ar += (t12r * t3r - t12i * t3i) * C;
                        ai += (t12r * t3i + t12i * t3r) * C;
                    }
                }
        }
        if (tid < 128) {
            sAr[tid] = (tid < tot) ? (float)fabs(ar) : 0.0f;
            sAi[tid] = (tid < tot) ? (float)fabs(ai) : 0.0f;
        }
        __syncthreads();
        if (tid == 0) {
            float sr = 0.0f, si = 0.0f;
            for (int q = 0; q < tot; q++) { sr += sAr[q]; si += sAi[q]; }
            *sUseRe = (sr >= si) ? 1 : 0;
        }
        __syncthreads();
        if (tid < tot)
            g_cg[CGO[p] + tid] = (float)(*sUseRe ? ar : ai);
        return;
    }
    b -= NB_CG;

    if (b < NB_TAB) {
        float* F = (float*)sbuf;
        float* sW1 = F;
        float* sB1 = F + 512;
        float* sB2 = F + 576;
        float* sW2 = F + 640;
        float* sW3 = F + 4736;
        float* sB3 = F + 5696;

        for (int i = tid; i < 8 * 64; i += 256) sW1[i] = fw1[i];
        for (int i = tid; i < 64; i += 256) { sB1[i] = fb1[i]; sB2[i] = fb2[i]; }
        for (int i = tid; i < 64 * 64; i += 256) sW2[i] = fw2[i];
        for (int i = tid; i < 64 * NPATHS; i += 256) sW3[i] = fw3[i];
        for (int i = tid; i < NPATHS; i += 256) sB3[i] = fb3[i];
        __syncthreads();

        int idx = b * 256 + tid;
        if (idx > TABN) return;
        float len = (float)idx * (2.0f / (float)TABN);

        float emb[8];
        const float step = 2.0f / 9.0f;
        const float istep = 4.5f;
        const float cemb = 2.8284271247461903f / 1.12f;
#pragma unroll
        for (int i = 0; i < 8; i++) {
            float t = (len - (float)(i + 1) * step) * istep;
            emb[i] = __expf(-t * t) * cemb;
        }

        float h1[64];
#pragma unroll
        for (int j = 0; j < 64; j++) {
            float t = sB1[j];
#pragma unroll
            for (int i = 0; i < 8; i++) t += emb[i] * sW1[i * 64 + j];
            h1[j] = t / (1.0f + __expf(-t));
        }

        float gp[NPATHS];
#pragma unroll
        for (int p = 0; p < NPATHS; p++) gp[p] = sB3[p];
#pragma unroll 4
        for (int j = 0; j < 64; j++) {
            float t = sB2[j];
#pragma unroll
            for (int i = 0; i < 64; i++) t += h1[i] * sW2[i * 64 + j];
            float s = t / (1.0f + __expf(-t));
#pragma unroll
            for (int p = 0; p < NPATHS; p++) gp[p] += s * sW3[j * NPATHS + p];
        }

        const float ALP0 = 0.20412414523193154f;
        const float ALP1 = 0.14433756729740643f;
        float* row = g_tab + (size_t)idx * 16;
#pragma unroll
        for (int p = 0; p < NPATHS; p++) {
            float alpha = (PL3[p] == 0) ? ALP0 : ALP1;
            row[p] = gp[p] * alpha * inv_avg;
        }
        row[15] = 0.0f;
        return;
    }
    b -= NB_TAB;

    if (b < nbNode) {
        float* F = (float*)sbuf;
        float* sW1 = F;
        float* sB1 = F + 1024;
        float* sW2 = F + 1088;
        float* sB2 = F + 1600;
        float* sEmb = F + 1608;

        for (int i = tid; i < 16 * 64; i += 256) sW1[i] = mw1[i];
        for (int i = tid; i < 64; i += 256) sB1[i] = mb1[i];
        for (int i = tid; i < 64 * 8; i += 256) sW2[i] = mw2[i];
        for (int i = tid; i < 8; i += 256) sB2[i] = mb2[i];
        for (int i = tid; i < 10 * 16; i += 256) sEmb[i] = emb_table[i];
        __syncthreads();

        int n = b * 256 + tid;
        if (n >= N) return;
        int a = A[n];
        float x[16];
#pragma unroll
        for (int i = 0; i < 16; i++) x[i] = sEmb[a * 16 + i];
        float h[64];
#pragma unroll
        for (int j = 0; j < 64; j++) {
            float t = sB1[j];
#pragma unroll
            for (int i = 0; i < 16; i++) t += x[i] * sW1[i * 64 + j];
            h[j] = t / (1.0f + __expf(-t));
        }
#pragma unroll
        for (int o = 0; o < 8; o++) {
            float t = sB2[o];
#pragma unroll
            for (int j = 0; j < 64; j++) t += h[j] * sW2[j * 8 + o];
            g_Ai[n * 8 + o] = t;
        }
        return;
    }
    b -= nbNode;

    if (b < nbHist) {
        int e = b * 256 + tid;
        if (e < E) atomicAdd(&g_count[edst[e]], 1);
        return;
    }
    b -= nbHist;

    // ----- fill dstS with -1 (pad marker); scatter overwrites real slots -----
    int i = b * 256 + tid;            // one int4 = 4 ints per thread
    if (i < EPAD / 4)
        ((int4*)g_dstS)[i] = make_int4(-1, -1, -1, -1);
}

// ---------------------------------------------------------------------------
// Coalesced exclusive scan over ALIGNED counts ((c+7)&~7). 8-aligned starts
// to g_off/g_cursor; re-zeros g_count.
// ---------------------------------------------------------------------------
__global__ void __launch_bounds__(1024) scan_kernel() {
    __shared__ int warpsums[32];
    __shared__ int sCarry;
    int t = threadIdx.x;
    int lane = t & 31, wid = t >> 5;
    if (t == 0) sCarry = 0;
    __syncthreads();

#pragma unroll 1
    for (int base = 0; base < NPAD; base += 4096) {
        int4 v = *(const int4*)(g_count + base + t * 4);
        *(int4*)(g_count + base + t * 4) = make_int4(0, 0, 0, 0);  // re-zero for next replay
        int4 pv;
        pv.x = (v.x + 7) & ~7;
        pv.y = (v.y + 7) & ~7;
        pv.z = (v.z + 7) & ~7;
        pv.w = (v.w + 7) & ~7;
        int s = pv.x + pv.y + pv.z + pv.w;
        int ss = s;
#pragma unroll
        for (int d = 1; d < 32; d <<= 1) {
            int o = __shfl_up_sync(0xffffffffu, ss, d);
            if (lane >= d) ss += o;
        }
        if (lane == 31) warpsums[wid] = ss;
        __syncthreads();
        if (wid == 0) {
            int w = warpsums[lane];
#pragma unroll
            for (int d = 1; d < 32; d <<= 1) {
                int o = __shfl_up_sync(0xffffffffu, w, d);
                if (lane >= d) w += o;
            }
            warpsums[lane] = w;
        }
        __syncthreads();
        int carry = sCarry;
        int excl = carry + (wid ? warpsums[wid - 1] : 0) + (ss - s);
        int4 o;
        o.x = excl;
        o.y = excl + pv.x;
        o.z = o.y + pv.y;
        o.w = o.z + pv.z;
        *(int4*)(g_off + base + t * 4) = o;
        *(int4*)(g_cursor + base + t * 4) = o;
        int total = warpsums[31];
        __syncthreads();
        if (t == 0) sCarry = carry + total;
        __syncthreads();
    }
    if (t == 0) g_off[NPAD] = sCarry;
}

// ---------------------------------------------------------------------------
// Scatter: write packed record + dst at padded cursor position.
// ---------------------------------------------------------------------------
__global__ void scatter_kernel(const int* __restrict__ esrc,
                               const int* __restrict__ edst,
                               const float* __restrict__ eshift, int E) {
    int e = blockIdx.x * blockDim.x + threadIdx.x;
    if (e >= E) return;
    int d = edst[e];
    int s = esrc[e];
    float sx = eshift[e * 3 + 0], sy = eshift[e * 3 + 1], sz = eshift[e * 3 + 2];
    int p = atomicAdd(&g_cursor[d], 1);
    g_edata[p] = make_float4(sx, sy, sz, __int_as_float(s));
    g_dstS[p] = d;
}

// ---------------------------------------------------------------------------
// Geo kernel: thread per PADDED slot; coalesced reads+writes. Pad slots
// (dstS < 0) write zero Ai rows (geoH pads stale-but-finite, annihilated).
// ---------------------------------------------------------------------------
__global__ void __launch_bounds__(256) geo_kernel(
    const float* __restrict__ pos, const int* __restrict__ batch,
    const float* __restrict__ cell, int padBound)
{
    __shared__ float sCG[CG_TOTAL];
    int tid = threadIdx.x;
    for (int i = tid; i < CG_TOTAL; i += 256) sCG[i] = g_cg[i];
    __syncthreads();

    int slot = blockIdx.x * 256 + tid;
    if (slot >= padBound) return;
    int d = g_dstS[slot];

    if (d < 0) {
        // pad slot: zero the Ai rows so accum contributions vanish
        __half z = __float2half_rn(0.0f);
#pragma unroll
        for (int m = 0; m < 8; m++)
            g_AiH[(size_t)m * EPAD + slot] = z;
        return;
    }

    float4 rec = g_edata[slot];
    int s = __float_as_int(rec.w);

    {
        const float4* ap = (const float4*)(g_Ai + (size_t)s * 8);
        float4 a0 = ap[0], a1 = ap[1];
        g_AiH[(size_t)0 * EPAD + slot] = __float2half_rn(a0.x);
        g_AiH[(size_t)1 * EPAD + slot] = __float2half_rn(a0.y);
        g_AiH[(size_t)2 * EPAD + slot] = __float2half_rn(a0.z);
        g_AiH[(size_t)3 * EPAD + slot] = __float2half_rn(a0.w);
        g_AiH[(size_t)4 * EPAD + slot] = __float2half_rn(a1.x);
        g_AiH[(size_t)5 * EPAD + slot] = __float2half_rn(a1.y);
        g_AiH[(size_t)6 * EPAD + slot] = __float2half_rn(a1.z);
        g_AiH[(size_t)7 * EPAD + slot] = __float2half_rn(a1.w);
    }

    int b = batch[s];
    const float* cl = cell + b * 9;
    float shx = rec.x * cl[0] + rec.y * cl[3] + rec.z * cl[6];
    float shy = rec.x * cl[1] + rec.y * cl[4] + rec.z * cl[7];
    float shz = rec.x * cl[2] + rec.y * cl[5] + rec.z * cl[8];
    float vx = pos[d * 3 + 0] - pos[s * 3 + 0] + shx;
    float vy = pos[d * 3 + 1] - pos[s * 3 + 1] + shy;
    float vz = pos[d * 3 + 2] - pos[s * 3 + 2] + shz;
    float L = sqrtf(vx * vx + vy * vy + vz * vz);
    float il = 1.0f / fmaxf(L, 1e-8f);
    float nx = vx * il, ny = vy * il, nz = vz * il;

    float Yv[9];
    const float s3 = 1.7320508075688772f;
    const float s15 = 3.872983346207417f;
    const float s5 = 2.23606797749979f;
    Yv[0] = 1.0f;
    Yv[1] = s3 * ny; Yv[2] = s3 * nz; Yv[3] = s3 * nx;
    Yv[4] = s15 * nx * ny;
    Yv[5] = s15 * ny * nz;
    Yv[6] = 0.5f * s5 * (3.0f * nz * nz - 1.0f);
    Yv[7] = s15 * nx * nz;
    Yv[8] = 0.5f * s15 * (nx * nx - ny * ny);

    float gp[16];
    {
        float t = L * ((float)TABN / 2.0f);
        int i0 = (int)t;
        i0 = min(i0, TABN - 1);
        float f = t - (float)i0;
        const float4* t0 = (const float4*)(g_tab + (size_t)i0 * 16);
        const float4* t1 = (const float4*)(g_tab + (size_t)(i0 + 1) * 16);
#pragma unroll
        for (int q = 0; q < 4; q++) {
            float4 a = t0[q], c = t1[q];
            gp[q * 4 + 0] = a.x + f * (c.x - a.x);
            gp[q * 4 + 1] = a.y + f * (c.y - a.y);
            gp[q * 4 + 2] = a.z + f * (c.z - a.z);
            gp[q * 4 + 3] = a.w + f * (c.w - a.w);
        }
    }

#pragma unroll
    for (int p = 0; p < NPATHS; p++) {
        const int l1 = PL1[p], l2 = PL2[p], l3 = PL3[p];
        const int o1 = LOFF[l1], o2 = LOFF[l2];
        const int n2d = 2 * l2 + 1, n3d = 2 * l3 + 1;
        float acc[5];
#pragma unroll
        for (int k = 0; k < 5; k++) acc[k] = 0.0f;
#pragma unroll
        for (int m = 0; m < 2 * l1 + 1; m++) {
#pragma unroll
            for (int n = 0; n < 2 * l2 + 1; n++) {
                float t = Yv[o1 + m] * Yv[o2 + n];
#pragma unroll
                for (int k = 0; k < 2 * l3 + 1; k++)
                    acc[k] += t * sCG[CGO[p] + (m * n2d + n) * n3d + k];
            }
        }
#pragma unroll
        for (int k = 0; k < 2 * l3 + 1; k++)
            g_geoH[(size_t)(GEOO[p] + k) * EPAD + slot] = __float2half_rn(acc[k] * gp[p]);
    }
}

// ---------------------------------------------------------------------------
// Accum+finalize: warp per node, ALL-VECTOR loop over the 8-aligned segment.
// ---------------------------------------------------------------------------
__global__ void __launch_bounds__(256) accum_finalize_kernel(
    const float* __restrict__ tpw, float* __restrict__ out, int N)
{
    __shared__ float sS[8][416];
    __shared__ float sTP[NPATHS * 8 * 16];
    int tid = threadIdx.x;
    for (int i = tid; i < NPATHS * 8 * 16; i += 256) sTP[i] = tpw[i];
    __syncthreads();

    int warp = tid >> 5;
    int lane = tid & 31;
    int n = blockIdx.x * 8 + warp;
    int m = lane & 7;
    int q = lane >> 3;           // 0..3
    int base_pj = q * 13;        // pj 51 is a zero row (padding)
    if (n >= N) return;

    {
        int lo = g_off[n], hi = g_off[n + 1];
        const __half* aim = g_AiH + (size_t)m * EPAD;

        float acc[13];
#pragma unroll
        for (int r = 0; r < 13; r++) acc[r] = 0.0f;

        for (int i = lo; i < hi; i += 8) {
            float4 av = *(const float4*)(aim + i);
            const __half2* ah = (const __half2*)&av;
            float af[8];
#pragma unroll
            for (int k = 0; k < 4; k++) {
                float2 f = __half22float2(ah[k]);
                af[2 * k] = f.x;
                af[2 * k + 1] = f.y;
            }
#pragma unroll
            for (int r = 0; r < 13; r++) {
                float4 gv = *(const float4*)(g_geoH + (size_t)(base_pj + r) * EPAD + i);
                const __half2* gh = (const __half2*)&gv;
#pragma unroll
                for (int k = 0; k < 4; k++) {
                    float2 gf = __half22float2(gh[k]);
                    acc[r] += af[2 * k] * gf.x + af[2 * k + 1] * gf.y;
                }
            }
        }

        float* srow = &sS[warp][m * 52 + base_pj];
#pragma unroll
        for (int r = 0; r < 13; r++) srow[r] = acc[r];
    }
    __syncwarp();

    if (lane >= 16) return;
    int c = lane;
    const float* S = sS[warp];
    float* orow = out + (size_t)n * 144;

    const int P0[3] = {0, 4, 12};
    const int G0[3] = {0, 12, 42};
    const int P1[6] = {1, 3, 5, 7, 10, 13};
    const int G1[6] = {1, 9, 13, 21, 34, 43};
    const int P2[6] = {2, 6, 8, 9, 11, 14};
    const int G2[6] = {4, 16, 24, 29, 37, 46};

    {
        float a = 0.0f;
#pragma unroll
        for (int i = 0; i < 3; i++) {
            int p = P0[i], g = G0[i];
#pragma unroll
            for (int m2 = 0; m2 < 8; m2++)
                a += sTP[(p * 8 + m2) * 16 + c] * S[m2 * 52 + g];
        }
        orow[c] = a;
    }
#pragma unroll
    for (int k = 0; k < 3; k++) {
        float a = 0.0f;
#pragma unroll
        for (int i = 0; i < 6; i++) {
            int p = P1[i], g = G1[i] + k;
#pragma unroll
            for (int m2 = 0; m2 < 8; m2++)
                a += sTP[(p * 8 + m2) * 16 + c] * S[m2 * 52 + g];
        }
        orow[16 + 3 * c + k] = a;
    }
#pragma unroll
    for (int k = 0; k < 5; k++) {
        float a = 0.0f;
#pragma unroll
        for (int i = 0; i < 6; i++) {
            int p = P2[i], g = G2[i] + k;
#pragma unroll
            for (int m2 = 0; m2 < 8; m2++)
                a += sTP[(p * 8 + m2) * 16 + c] * S[m2 * 52 + g];
        }
        orow[64 + 5 * c + k] = a;
    }
}

// ---------------------------------------------------------------------------
extern "C" void kernel_launch(void* const* d_in, const int* in_sizes, int n_in,
                              void* d_out, int out_size)
{
    const float* pos    = (const float*)d_in[0];
    const int*   A      = (const int*)d_in[1];
    const int*   batch  = (const int*)d_in[2];
    const int*   esrc   = (const int*)d_in[3];
    const int*   edst   = (const int*)d_in[4];
    const float* eshift = (const float*)d_in[5];
    const float* cell   = (const float*)d_in[6];
    const float* embt   = (const float*)d_in[7];
    const float* mw1    = (const float*)d_in[8];
    const float* mb1    = (const float*)d_in[9];
    const float* mw2    = (const float*)d_in[10];
    const float* mb2    = (const float*)d_in[11];
    const float* fw1    = (const float*)d_in[12];
    const float* fb1    = (const float*)d_in[13];
    const float* fw2    = (const float*)d_in[14];
    const float* fb2    = (const float*)d_in[15];
    const float* fw3    = (const float*)d_in[16];
    const float* fb3    = (const float*)d_in[17];
    const float* tpw    = (const float*)d_in[18];
    float* out = (float*)d_out;

    int N = in_sizes[1];
    int E = in_sizes[3];
    float avg = (float)E / (float)N;
    float inv_avg = 1.0f / fmaxf(avg, 1e-8f);

    int nbNode = (N + 255) / 256;
    int nbHist = (E + 255) / 256;
    int nbFill = (EPAD / 4 + 255) / 256;
    int megaBlocks = NB_CG + NB_TAB + nbNode + nbHist + nbFill;

    // upper bound on total padded slots: E + 8 per node (cap EPAD)
    long long pb = (long long)E + 8LL * N;
    int padBound = (pb > EPAD) ? EPAD : (int)pb;

    mega_init_kernel<<<megaBlocks, 256>>>(fw1, fb1, fw2, fb2, fw3, fb3, inv_avg,
                                          embt, A, mw1, mb1, mw2, mb2, edst,
                                          N, E, nbNode, nbHist);
    scan_kernel<<<1, 1024>>>();
    scatter_kernel<<<(E + 255) / 256, 256>>>(esrc, edst, eshift, E);
    geo_kernel<<<(padBound + 255) / 256, 256>>>(pos, batch, cell, padBound);
    accum_finalize_kernel<<<(N + 7) / 8, 256>>>(tpw, out, N);
}